// round 2
// baseline (speedup 1.0000x reference)
#include <cuda_runtime.h>
#include <math.h>

// Problem constants (fixed shapes from reference: B=8, C=256, H=W=64)
#define B_  8
#define C_  256
#define E_  128
#define HW_ 4096
#define BM  64
#define BN  64

#define QK_PITCH 132   // [m][e] rows, 128 floats + 4 pad (float4 aligned, conflict-free fills)
#define V_PITCH  260   // [k][c] rows, 256 floats + 4 pad
#define P_PITCH  68    // [k][m] rows, 64 floats + 4 pad
#define L_PITCH  68    // proj: [c][q]
#define W_PITCH  68    // proj: [c][e-chunk]

// -------- scratch (allocation-free: __device__ globals) --------
__device__ float g_thetaT[(size_t)B_ * HW_ * E_];   // [b][q][e]
__device__ float g_phiT  [(size_t)B_ * HW_ * E_];   // [b][k][e]
__device__ float g_wT    [2 * C_ * E_];             // [mat][c][e]

// -------- 1) transpose weights: w[e][c] -> wT[c][e] --------
__global__ void transpose_w_kernel(const float* __restrict__ wt,
                                   const float* __restrict__ wp) {
    int idx = blockIdx.x * blockDim.x + threadIdx.x;   // 0 .. 32767
    int e = idx >> 8;          // /256
    int c = idx & 255;
    g_wT[c * E_ + e]            = wt[idx];
    g_wT[C_ * E_ + c * E_ + e]  = wp[idx];
}

// -------- 2) projection: theta/phi = wT^T * l  (per batch) --------
// grid (HW/64, B), block 256. Output theta_T[b][q][e], phi_T[b][k][e].
__global__ __launch_bounds__(256, 1)
void proj_kernel(const float* __restrict__ l) {
    extern __shared__ float sm[];
    float* Ls = sm;                    // [256][L_PITCH]  l[c][q] tile
    float* Ws = Ls + C_ * L_PITCH;     // [256][W_PITCH]  wT[c][e-chunk]

    const int b  = blockIdx.y;
    const int q0 = blockIdx.x * 64;
    const int t  = threadIdx.x;
    const int tx = t & 15, ty = t >> 4;

    // load Ls[c][q] for all 256 c, 64 q (coalesced float4)
    {
        const int qg = t & 15;
        const int c  = t >> 4;
        const float* lb = l + (size_t)b * C_ * HW_ + q0 + 4 * qg;
        #pragma unroll
        for (int cc = c; cc < C_; cc += 16) {
            float4 v = *(const float4*)(lb + (size_t)cc * HW_);
            *(float4*)(Ls + cc * L_PITCH + 4 * qg) = v;
        }
    }

    #pragma unroll
    for (int mat = 0; mat < 2; mat++) {
        const float* wT = g_wT + mat * C_ * E_;
        float* outT = (mat == 0 ? g_thetaT : g_phiT) + (size_t)b * HW_ * E_;
        #pragma unroll
        for (int e0 = 0; e0 < E_; e0 += 64) {
            __syncthreads();   // protect Ws reuse (and Ls fill on first pass)
            {
                const int g = t & 15;
                const int c = t >> 4;
                #pragma unroll
                for (int cc = c; cc < C_; cc += 16) {
                    float4 v = *(const float4*)(wT + cc * E_ + e0 + 4 * g);
                    *(float4*)(Ws + cc * W_PITCH + 4 * g) = v;
                }
            }
            __syncthreads();

            float acc[4][4];
            #pragma unroll
            for (int i = 0; i < 4; i++)
                #pragma unroll
                for (int j = 0; j < 4; j++) acc[i][j] = 0.f;

            for (int c = 0; c < C_; c++) {
                float lv[4], wv[4];
                #pragma unroll
                for (int i = 0; i < 4; i++) lv[i] = Ls[c * L_PITCH + ty + 16 * i];
                #pragma unroll
                for (int j = 0; j < 4; j++) wv[j] = Ws[c * W_PITCH + tx + 16 * j];
                #pragma unroll
                for (int i = 0; i < 4; i++)
                    #pragma unroll
                    for (int j = 0; j < 4; j++) acc[i][j] += lv[i] * wv[j];
            }
            #pragma unroll
            for (int i = 0; i < 4; i++) {
                const int q = q0 + ty + 16 * i;
                #pragma unroll
                for (int j = 0; j < 4; j++)
                    outT[(size_t)q * E_ + e0 + tx + 16 * j] = acc[i][j];
            }
        }
    }
}

// -------- 3) flash attention --------
// grid (HW/BM, B), block 256 (16x16). Thread (ty,tx):
//   S tile rows  m = ty + 16*i (i<4), cols n = tx + 16*j (j<4)
//   O tile rows  m,               cols c = 16*tx + jj (jj<16)
__global__ __launch_bounds__(256, 1)
void flash_kernel(const float* __restrict__ l, float* __restrict__ out) {
    extern __shared__ float sm[];
    float* Qs = sm;                      // [64][QK_PITCH]  theta[q][e]
    float* Ks = Qs + BM * QK_PITCH;      // [64][QK_PITCH]  phi[k][e]
    float* Vs = Ks + BN * QK_PITCH;      // [64][V_PITCH]   l^T[k][c]
    float* Ps = Vs + BN * V_PITCH;       // [64][P_PITCH]   P^T[k][m]

    const int b  = blockIdx.y;
    const int q0 = blockIdx.x * BM;
    const int t  = threadIdx.x;
    const int tx = t & 15, ty = t >> 4;

    const float* thetaB = g_thetaT + (size_t)b * HW_ * E_;
    const float* phiB   = g_phiT   + (size_t)b * HW_ * E_;
    const float* lB     = l + (size_t)b * C_ * HW_;

    // load Q tile once: Qs[m][e]
    {
        const int g = t & 31;
        const int m = t >> 5;
        #pragma unroll
        for (int mm = m; mm < BM; mm += 8) {
            float4 v = *(const float4*)(thetaB + (size_t)(q0 + mm) * E_ + 4 * g);
            *(float4*)(Qs + mm * QK_PITCH + 4 * g) = v;
        }
    }

    float O[4][16];
    float mrow[4], lrow[4];
    #pragma unroll
    for (int i = 0; i < 4; i++) {
        mrow[i] = -1e30f;
        lrow[i] = 0.f;
        #pragma unroll
        for (int jj = 0; jj < 16; jj++) O[i][jj] = 0.f;
    }

    const float scale = 0.088388347648318447f;  // 1/sqrt(128)

    for (int k0 = 0; k0 < HW_; k0 += BN) {
        __syncthreads();  // previous PV done before K/V overwrite; first iter: Q fill done

        // load K tile: Ks[n][e]
        {
            const int g = t & 31;
            const int n = t >> 5;
            #pragma unroll
            for (int nn = n; nn < BN; nn += 8) {
                float4 v = *(const float4*)(phiB + (size_t)(k0 + nn) * E_ + 4 * g);
                *(float4*)(Ks + nn * QK_PITCH + 4 * g) = v;
            }
        }
        // load V tile transposed: Vs[k][c] = l[b][c][k0+k]
        {
            const int k  = t & 63;
            const int cg = t >> 6;           // 0..3
            const float* lk = lB + k0 + k;
            #pragma unroll
            for (int c0 = 0; c0 < C_; c0 += 16) {
                const int c = c0 + 4 * cg;
                float v0 = lk[(size_t)(c + 0) * HW_];
                float v1 = lk[(size_t)(c + 1) * HW_];
                float v2 = lk[(size_t)(c + 2) * HW_];
                float v3 = lk[(size_t)(c + 3) * HW_];
                *(float4*)(Vs + k * V_PITCH + c) = make_float4(v0, v1, v2, v3);
            }
        }
        __syncthreads();

        // S = Q K^T  (reduce over e, float4-unrolled)
        float s[4][4];
        #pragma unroll
        for (int i = 0; i < 4; i++)
            #pragma unroll
            for (int j = 0; j < 4; j++) s[i][j] = 0.f;

        for (int e = 0; e < E_; e += 4) {
            float4 qv[4], kv[4];
            #pragma unroll
            for (int i = 0; i < 4; i++)
                qv[i] = *(const float4*)(Qs + (ty + 16 * i) * QK_PITCH + e);
            #pragma unroll
            for (int j = 0; j < 4; j++)
                kv[j] = *(const float4*)(Ks + (tx + 16 * j) * QK_PITCH + e);
            #pragma unroll
            for (int i = 0; i < 4; i++)
                #pragma unroll
                for (int j = 0; j < 4; j++) {
                    s[i][j] += qv[i].x * kv[j].x;
                    s[i][j] += qv[i].y * kv[j].y;
                    s[i][j] += qv[i].z * kv[j].z;
                    s[i][j] += qv[i].w * kv[j].w;
                }
        }

        // online softmax (row stats replicated across the 16 tx threads of each row)
        #pragma unroll
        for (int i = 0; i < 4; i++) {
            float mx = -1e30f;
            #pragma unroll
            for (int j = 0; j < 4; j++) {
                s[i][j] *= scale;
                mx = fmaxf(mx, s[i][j]);
            }
            #pragma unroll
            for (int o = 1; o < 16; o <<= 1)
                mx = fmaxf(mx, __shfl_xor_sync(0xffffffffu, mx, o));
            const float mnew = fmaxf(mrow[i], mx);
            const float cf   = __expf(mrow[i] - mnew);
            mrow[i] = mnew;
            float rs = 0.f;
            #pragma unroll
            for (int j = 0; j < 4; j++) {
                const float p = __expf(s[i][j] - mnew);
                s[i][j] = p;
                rs += p;
            }
            #pragma unroll
            for (int o = 1; o < 16; o <<= 1)
                rs += __shfl_xor_sync(0xffffffffu, rs, o);
            lrow[i] = lrow[i] * cf + rs;
            #pragma unroll
            for (int jj = 0; jj < 16; jj++) O[i][jj] *= cf;
        }

        // store P transposed: Ps[n][m]
        #pragma unroll
        for (int j = 0; j < 4; j++)
            #pragma unroll
            for (int i = 0; i < 4; i++)
                Ps[(tx + 16 * j) * P_PITCH + (ty + 16 * i)] = s[i][j];
        __syncthreads();

        // O += P * V
        for (int k = 0; k < BN; k++) {
            float p[4];
            #pragma unroll
            for (int i = 0; i < 4; i++) p[i] = Ps[k * P_PITCH + ty + 16 * i];
            #pragma unroll
            for (int j4 = 0; j4 < 4; j4++) {
                float4 v = *(const float4*)(Vs + k * V_PITCH + 16 * tx + 4 * j4);
                #pragma unroll
                for (int i = 0; i < 4; i++) {
                    O[i][4 * j4 + 0] += p[i] * v.x;
                    O[i][4 * j4 + 1] += p[i] * v.y;
                    O[i][4 * j4 + 2] += p[i] * v.z;
                    O[i][4 * j4 + 3] += p[i] * v.w;
                }
            }
        }
    }

    // epilogue: out[b][c][q] = O[q][c] / l_q
    #pragma unroll
    for (int i = 0; i < 4; i++) {
        const float inv = 1.0f / lrow[i];
        const int q = q0 + ty + 16 * i;
        #pragma unroll
        for (int jj = 0; jj < 16; jj++) {
            const int c = 16 * tx + jj;
            out[(size_t)b * C_ * HW_ + (size_t)c * HW_ + q] = O[i][jj] * inv;
        }
    }
}

// -------- launch --------
extern "C" void kernel_launch(void* const* d_in, const int* in_sizes, int n_in,
                              void* d_out, int out_size) {
    const float* l  = (const float*)d_in[0];
    const float* wt = (const float*)d_in[1];
    const float* wp = (const float*)d_in[2];
    float* out = (float*)d_out;

    const int proj_smem  = (C_ * L_PITCH + C_ * W_PITCH) * (int)sizeof(float);          // 139,264 B
    const int flash_smem = (BM * QK_PITCH + BN * QK_PITCH + BN * V_PITCH + BN * P_PITCH)
                           * (int)sizeof(float);                                        // 151,552 B

    cudaFuncSetAttribute(proj_kernel,  cudaFuncAttributeMaxDynamicSharedMemorySize, proj_smem);
    cudaFuncSetAttribute(flash_kernel, cudaFuncAttributeMaxDynamicSharedMemorySize, flash_smem);

    transpose_w_kernel<<<128, 256>>>(wt, wp);
    proj_kernel<<<dim3(HW_ / 64, B_), 256, proj_smem>>>(l);
    flash_kernel<<<dim3(HW_ / BM, B_), 256, flash_smem>>>(l, out);
}